// round 5
// baseline (speedup 1.0000x reference)
#include <cuda_runtime.h>
#include <cuda_fp16.h>
#include <cstdint>

// LSTMClassifier B=2048,T=256,F=64,H=128 via mma.sync (HMMA) on sm_103.
// 512 threads / 16 warps per block, 16 batch rows per block.
// Warp w: unit-group ug=w&7 (16 units), gate-pair gp=w>>3 (i,f | g,o).
// W_hh fragments resident in registers; W_ih + inputs from smem.
// Gate exchange gp0->gp1 via padded smem; gp1 owns cell state.

#define T_STEPS 256
#define FDIM 64
#define HDIM 128
#define ROWS 16
#define NBLOCKS 128
#define NTHREADS 512

// smem byte offsets
#define AW_OFF   0                        // 512x192 fp16 A tiles = 196608
#define INT_OFF  196608                   // in^T: 192 k-rows x 32B = 6144
#define XCHG_OFF 202752                   // gate exchange, padded = 17408
#define HS_OFF   220160                   // final h fp32 [128 u][16 r] = 8192
#define SMEM_TOTAL 228352

__device__ __forceinline__ uint32_t smem_u32(const void* p) {
    uint32_t a;
    asm("{ .reg .u64 t; cvta.to.shared.u64 t, %1; cvt.u32.u64 %0, t; }" : "=r"(a) : "l"(p));
    return a;
}

#define LDSM_X4(r0, r1, r2, r3, a) \
    asm volatile("ldmatrix.sync.aligned.m8n8.x4.shared.b16 {%0,%1,%2,%3}, [%4];" \
                 : "=r"(r0), "=r"(r1), "=r"(r2), "=r"(r3) : "r"(a))

#define LDSM_X4_T(r0, r1, r2, r3, a) \
    asm volatile("ldmatrix.sync.aligned.m8n8.x4.trans.shared.b16 {%0,%1,%2,%3}, [%4];" \
                 : "=r"(r0), "=r"(r1), "=r"(r2), "=r"(r3) : "r"(a))

#define MMA16816(d, a0, a1, a2, a3, b0, b1) \
    asm volatile("mma.sync.aligned.m16n8k16.row.col.f32.f16.f16.f32 " \
                 "{%0,%1,%2,%3}, {%4,%5,%6,%7}, {%8,%9}, {%0,%1,%2,%3};" \
                 : "+f"((d)[0]), "+f"((d)[1]), "+f"((d)[2]), "+f"((d)[3]) \
                 : "r"(a0), "r"(a1), "r"(a2), "r"(a3), "r"(b0), "r"(b1))

__device__ __forceinline__ float sigm(float v) {
    float e = __expf(-v);
    return __fdividef(1.0f, 1.0f + e);
}
__device__ __forceinline__ float tanh_e(float v) {
    float a = fabsf(v);
    float e = __expf(-2.0f * a);
    float r = __fdividef(1.0f - e, 1.0f + e);
    return copysignf(r, v);
}

__global__ __launch_bounds__(NTHREADS, 1) void lstm_mma_kernel(
    const float* __restrict__ x,
    const float* __restrict__ Wih, const float* __restrict__ Whh,
    const float* __restrict__ bih, const float* __restrict__ bhh,
    const float* __restrict__ W1, const float* __restrict__ b1,
    const float* __restrict__ W2, const float* __restrict__ b2,
    float* __restrict__ out)
{
    extern __shared__ char smem[];
    const uint32_t sb = smem_u32(smem);
    const int tid  = threadIdx.x;
    const int wid  = tid >> 5;
    const int lane = tid & 31;
    const int b0   = blockIdx.x * ROWS;

    const int ug = wid & 7;               // unit group: units ug*16..+15
    const int gp = wid >> 3;              // 0: gates (i,f)=q0,1  1: (g,o)=q2,3
    const int q0 = gp * 2, q1 = gp * 2 + 1;

    // ---- stage W_ih|W_hh fp32 -> fp16 swizzled 16x16 tiles in smem ----
    // Tile (wo, q, kt): base ((wo*4+q)*12+kt)*512; halfpair (j, kl) at
    // j*32 + ((kl>>3)^((j>>2)&1))*16 + (kl&7)*2.
    for (int i = tid; i < 512 * 96; i += NTHREADS) {
        int row = i / 96;                 // 0..511 = q*128 + u
        int kp  = (i - row * 96) * 2;     // 0..190 even
        int q = row >> 7, u = row & 127;
        int wo = u >> 4, j = u & 15;
        int kt = kp >> 4, kl = kp & 15;
        float2 v;
        if (kp < FDIM) v = *(const float2*)(Wih + row * FDIM + kp);
        else           v = *(const float2*)(Whh + row * HDIM + (kp - FDIM));
        uint32_t addr = (uint32_t)(((wo * 4 + q) * 12 + kt) * 512
                        + j * 32 + (((kl >> 3) ^ ((j >> 2) & 1)) << 4) + (kl & 7) * 2);
        *(__half2*)(smem + AW_OFF + addr) = __floats2half2_rn(v.x, v.y);
    }
    // zero h region of in^T (k-rows 64..191)
    for (int i = tid; i < 1024; i += NTHREADS)
        ((uint32_t*)(smem + INT_OFF + 2048))[i] = 0;

    // ---- per-thread frag addressing (as validated in round 4) ----
    const int s = lane >> 3, jj = lane & 7;
    const int Ja = ((s & 1) << 3) + jj;
    const uint32_t a_lane = (uint32_t)(Ja * 32 + ((((s >> 1)) ^ ((Ja >> 2) & 1)) << 4));
    const int kb = ((s & 1) << 3) + jj;
    const uint32_t b_base = sb + INT_OFF
        + (uint32_t)(kb * 32 + ((((s >> 1)) ^ ((kb >> 2) & 1)) << 4));

    const int g  = lane >> 2;             // d-frag row (0..7)
    const int cq = lane & 3;              // d-frag col pair
    const int u0 = ug * 16 + g;           // unit for jh=0 (+8 for jh=1)

    // biases for this warp's two gates, rows g and g+8
    const float b0L = bih[q0 * HDIM + u0]     + bhh[q0 * HDIM + u0];
    const float b0H = bih[q0 * HDIM + u0 + 8] + bhh[q0 * HDIM + u0 + 8];
    const float b1L = bih[q1 * HDIM + u0]     + bhh[q1 * HDIM + u0];
    const float b1H = bih[q1 * HDIM + u0 + 8] + bhh[q1 * HDIM + u0 + 8];

    // h write-back addresses (gp1 only uses these): k-row 64+u, fp16 half2
    uint32_t h_addr[2][2];
#pragma unroll
    for (int nt = 0; nt < 2; nt++)
#pragma unroll
        for (int jh = 0; jh < 2; jh++)
            h_addr[nt][jh] = sb + INT_OFF
                + (uint32_t)((64 + u0 + jh * 8) * 32
                + ((nt ^ ((g >> 2) & 1)) << 4) + cq * 4);

    // exchange addresses: float2 at ((ug*16 + j)*17 + r)*8
    uint32_t xg_addr[2][2][2];
#pragma unroll
    for (int nt = 0; nt < 2; nt++)
#pragma unroll
        for (int jh = 0; jh < 2; jh++)
#pragma unroll
            for (int ci = 0; ci < 2; ci++) {
                int j = g + jh * 8;
                int r = nt * 8 + cq * 2 + ci;
                xg_addr[nt][jh][ci] = sb + XCHG_OFF
                    + (uint32_t)(((ug * 16 + j) * 17 + r) * 8);
            }

    __syncthreads();

    // ---- preload W_hh A-fragments into registers (kt 4..11) ----
    uint32_t ah0[8][4], ah1[8][4];
#pragma unroll
    for (int kt = 0; kt < 8; kt++) {
        LDSM_X4(ah0[kt][0], ah0[kt][1], ah0[kt][2], ah0[kt][3],
                sb + AW_OFF + (uint32_t)(((ug * 4 + q0) * 12 + 4 + kt) * 512) + a_lane);
        LDSM_X4(ah1[kt][0], ah1[kt][1], ah1[kt][2], ah1[kt][3],
                sb + AW_OFF + (uint32_t)(((ug * 4 + q1) * 12 + 4 + kt) * 512) + a_lane);
    }

    // ---- x publish setup (gp0 threads only: tid 0..255) ----
    // thread covers batch row = tid&15, feature quad kq = (tid>>4)&15
    const int xrow = tid & 15, kq = (tid >> 4) & 15;
    const float* xptr = x + ((size_t)(b0 + xrow) * T_STEPS) * FDIM + kq * 4;
    uint32_t xs_addr[4];
#pragma unroll
    for (int i = 0; i < 4; i++) {
        int k = kq * 4 + i;
        xs_addr[i] = sb + INT_OFF
            + (uint32_t)(k * 32 + (((xrow >> 3) ^ ((k >> 2) & 1)) << 4) + (xrow & 7) * 2);
    }

    float cs[8];
#pragma unroll
    for (int i = 0; i < 8; i++) cs[i] = 0.0f;

    float4 xr;
    if (gp == 0) xr = *(const float4*)xptr;       // t = 0

    for (int t = 0; t < T_STEPS; t++) {
        // ---- gp0: publish x_t (fp16, swizzled) ----
        if (gp == 0) {
            *(__half*)(smem + (xs_addr[0] - sb)) = __float2half_rn(xr.x);
            *(__half*)(smem + (xs_addr[1] - sb)) = __float2half_rn(xr.y);
            *(__half*)(smem + (xs_addr[2] - sb)) = __float2half_rn(xr.z);
            *(__half*)(smem + (xs_addr[3] - sb)) = __float2half_rn(xr.w);
        }
        __syncthreads();                  // x_t + h_{t-1} visible

        // ---- D init with bias ----
        float D0[8], D1[8];
#pragma unroll
        for (int nt = 0; nt < 2; nt++) {
            D0[nt * 4 + 0] = b0L; D0[nt * 4 + 1] = b0L;
            D0[nt * 4 + 2] = b0H; D0[nt * 4 + 3] = b0H;
            D1[nt * 4 + 0] = b1L; D1[nt * 4 + 1] = b1L;
            D1[nt * 4 + 2] = b1H; D1[nt * 4 + 3] = b1H;
        }

        // ---- x part: kt 0..3, A from smem ----
#pragma unroll
        for (int kt = 0; kt < 4; kt++) {
            uint32_t v0, v1, v2, v3;
            LDSM_X4_T(v0, v1, v2, v3, b_base + kt * 512);
            uint32_t a0, a1, a2, a3;
            LDSM_X4(a0, a1, a2, a3,
                sb + AW_OFF + (uint32_t)(((ug * 4 + q0) * 12 + kt) * 512) + a_lane);
            MMA16816(&D0[0], a0, a1, a2, a3, v0, v1);
            MMA16816(&D0[4], a0, a1, a2, a3, v2, v3);
            LDSM_X4(a0, a1, a2, a3,
                sb + AW_OFF + (uint32_t)(((ug * 4 + q1) * 12 + kt) * 512) + a_lane);
            MMA16816(&D1[0], a0, a1, a2, a3, v0, v1);
            MMA16816(&D1[4], a0, a1, a2, a3, v2, v3);
        }
        // ---- h part: kt 4..11, A from registers ----
#pragma unroll
        for (int kt = 0; kt < 8; kt++) {
            uint32_t v0, v1, v2, v3;
            LDSM_X4_T(v0, v1, v2, v3, b_base + (4 + kt) * 512);
            MMA16816(&D0[0], ah0[kt][0], ah0[kt][1], ah0[kt][2], ah0[kt][3], v0, v1);
            MMA16816(&D0[4], ah0[kt][0], ah0[kt][1], ah0[kt][2], ah0[kt][3], v2, v3);
            MMA16816(&D1[0], ah1[kt][0], ah1[kt][1], ah1[kt][2], ah1[kt][3], v0, v1);
            MMA16816(&D1[4], ah1[kt][0], ah1[kt][1], ah1[kt][2], ah1[kt][3], v2, v3);
        }

        float tg[8], so[8];
        if (gp == 0) {
            // sigmoid(i), sigmoid(f) -> exchange
#pragma unroll
            for (int nt = 0; nt < 2; nt++)
#pragma unroll
                for (int jh = 0; jh < 2; jh++)
#pragma unroll
                    for (int ci = 0; ci < 2; ci++) {
                        int idx = nt * 4 + jh * 2 + ci;
                        float2 v;
                        v.x = sigm(D0[idx]);
                        v.y = sigm(D1[idx]);
                        *(float2*)(smem + (xg_addr[nt][jh][ci] - sb)) = v;
                    }
            // prefetch next x while gp1 works
            if (t + 1 < T_STEPS) xr = *(const float4*)(xptr + (size_t)(t + 1) * FDIM);
        } else {
            // tanh(g), sigmoid(o)
#pragma unroll
            for (int i = 0; i < 8; i++) {
                tg[i] = tanh_e(D0[i]);
                so[i] = sigm(D1[i]);
            }
        }
        __syncthreads();                  // exchange published; all MMA reads done

        if (gp == 1) {
#pragma unroll
            for (int nt = 0; nt < 2; nt++)
#pragma unroll
                for (int jh = 0; jh < 2; jh++) {
                    float h2[2];
#pragma unroll
                    for (int ci = 0; ci < 2; ci++) {
                        int idx = nt * 4 + jh * 2 + ci;
                        float2 sif = *(const float2*)(smem + (xg_addr[nt][jh][ci] - sb));
                        cs[idx] = sif.y * cs[idx] + sif.x * tg[idx];
                        float h = so[idx] * tanh_e(cs[idx]);
                        h2[ci] = h;
                        if (t == T_STEPS - 1) {
                            int u = u0 + jh * 8;
                            int r = nt * 8 + cq * 2 + ci;
                            *(float*)(smem + HS_OFF + (u * 16 + r) * 4) = h;
                        }
                    }
                    *(__half2*)(smem + (h_addr[nt][jh] - sb)) =
                        __floats2half2_rn(h2[0], h2[1]);
                }
        }
    }
    __syncthreads();

    // ---- head: Linear(128,32) -> ReLU -> Linear(32,1) -> Sigmoid ----
    float* W1t = (float*)(smem + AW_OFF);         // reuse weight region
    float* zS  = (float*)(smem + XCHG_OFF);       // 16x32 fp32
    const float* hs = (const float*)(smem + HS_OFF);
    for (int i = tid; i < 32 * HDIM; i += NTHREADS) {
        int m = i >> 7, k = i & 127;
        W1t[k * 32 + m] = W1[i];
    }
    __syncthreads();
    {
        int m = tid & 31, r = (tid >> 5) & 15;
        float z = b1[m];
        for (int k = 0; k < HDIM; k++)
            z += hs[k * 16 + r] * W1t[k * 32 + m];
        zS[r * 32 + m] = fmaxf(z, 0.0f);
    }
    __syncthreads();
    if (tid < ROWS) {
        float ssum = b2[0];
#pragma unroll
        for (int mm = 0; mm < 32; mm++) ssum += zS[tid * 32 + mm] * W2[mm];
        out[b0 + tid] = sigm(ssum);
    }
}

extern "C" void kernel_launch(void* const* d_in, const int* in_sizes, int n_in,
                              void* d_out, int out_size) {
    (void)in_sizes; (void)n_in; (void)out_size;
    const float* x   = (const float*)d_in[0];
    const float* Wih = (const float*)d_in[1];
    const float* Whh = (const float*)d_in[2];
    const float* bih = (const float*)d_in[3];
    const float* bhh = (const float*)d_in[4];
    const float* W1  = (const float*)d_in[5];
    const float* b1  = (const float*)d_in[6];
    const float* W2  = (const float*)d_in[7];
    const float* b2  = (const float*)d_in[8];
    float* out = (float*)d_out;

    cudaFuncSetAttribute(lstm_mma_kernel,
                         cudaFuncAttributeMaxDynamicSharedMemorySize, SMEM_TOTAL);
    lstm_mma_kernel<<<NBLOCKS, NTHREADS, SMEM_TOTAL>>>(
        x, Wih, Whh, bih, bhh, W1, b1, W2, b2, out);
}

// round 6
// speedup vs baseline: 1.1795x; 1.1795x over previous
#include <cuda_runtime.h>
#include <cuda_fp16.h>
#include <cstdint>

// LSTMClassifier B=2048,T=256,F=64,H=128 via mma.sync (HMMA) on sm_103.
// 512 threads / 16 warps per block, 16 batch rows per block.
// Warp w: unit-group ug=w&7 (16 units), gate-pair gp=w>>3 (i,f | g,o).
// W_hh fragments resident in registers; W_ih + inputs from smem.
// tanh.approx activations; x-GEMM pipelined into the epilogue phase.

#define T_STEPS 256
#define FDIM 64
#define HDIM 128
#define ROWS 16
#define NBLOCKS 128
#define NTHREADS 512

// smem byte offsets
#define AW_OFF   0                        // 512x192 fp16 A tiles = 196608
#define HB_OFF   196608                   // h^T: 128 k-rows x 32B = 4096
#define XB_OFF   200704                   // x^T double buffer: 2 x 2048
#define XCHG_OFF 204800                   // gate exchange, padded = 17408
#define HS_OFF   222208                   // final h fp32 [128 u][16 r] = 8192
#define SMEM_TOTAL 230400

__device__ __forceinline__ uint32_t smem_u32(const void* p) {
    uint32_t a;
    asm("{ .reg .u64 t; cvta.to.shared.u64 t, %1; cvt.u32.u64 %0, t; }" : "=r"(a) : "l"(p));
    return a;
}

#define LDSM_X4(r0, r1, r2, r3, a) \
    asm volatile("ldmatrix.sync.aligned.m8n8.x4.shared.b16 {%0,%1,%2,%3}, [%4];" \
                 : "=r"(r0), "=r"(r1), "=r"(r2), "=r"(r3) : "r"(a))

#define LDSM_X4_T(r0, r1, r2, r3, a) \
    asm volatile("ldmatrix.sync.aligned.m8n8.x4.trans.shared.b16 {%0,%1,%2,%3}, [%4];" \
                 : "=r"(r0), "=r"(r1), "=r"(r2), "=r"(r3) : "r"(a))

#define MMA16816(d, a0, a1, a2, a3, b0, b1) \
    asm volatile("mma.sync.aligned.m16n8k16.row.col.f32.f16.f16.f32 " \
                 "{%0,%1,%2,%3}, {%4,%5,%6,%7}, {%8,%9}, {%0,%1,%2,%3};" \
                 : "+f"((d)[0]), "+f"((d)[1]), "+f"((d)[2]), "+f"((d)[3]) \
                 : "r"(a0), "r"(a1), "r"(a2), "r"(a3), "r"(b0), "r"(b1))

__device__ __forceinline__ float tanh_a(float x) {
    float r;
    asm("tanh.approx.f32 %0, %1;" : "=f"(r) : "f"(x));
    return r;
}
__device__ __forceinline__ float sigm_a(float x) {
    return fmaf(tanh_a(0.5f * x), 0.5f, 0.5f);
}
__device__ __forceinline__ float sigm_exact(float v) {
    float e = __expf(-v);
    return __fdividef(1.0f, 1.0f + e);
}

__global__ __launch_bounds__(NTHREADS, 1) void lstm_mma_kernel(
    const float* __restrict__ x,
    const float* __restrict__ Wih, const float* __restrict__ Whh,
    const float* __restrict__ bih, const float* __restrict__ bhh,
    const float* __restrict__ W1, const float* __restrict__ b1,
    const float* __restrict__ W2, const float* __restrict__ b2,
    float* __restrict__ out)
{
    extern __shared__ char smem[];
    const uint32_t sb = smem_u32(smem);
    const int tid  = threadIdx.x;
    const int wid  = tid >> 5;
    const int lane = tid & 31;
    const int b0   = blockIdx.x * ROWS;

    const int ug = wid & 7;               // unit group: units ug*16..+15
    const int gp = wid >> 3;              // 0: gates (i,f)  1: (g,o)
    const int q0 = gp * 2, q1 = gp * 2 + 1;

    // ---- stage W_ih|W_hh fp32 -> fp16 swizzled 16x16 tiles in smem ----
    for (int i = tid; i < 512 * 96; i += NTHREADS) {
        int row = i / 96;                 // 0..511 = q*128 + u
        int kp  = (i - row * 96) * 2;     // 0..190 even
        int q = row >> 7, u = row & 127;
        int wo = u >> 4, j = u & 15;
        int kt = kp >> 4, kl = kp & 15;
        float2 v;
        if (kp < FDIM) v = *(const float2*)(Wih + row * FDIM + kp);
        else           v = *(const float2*)(Whh + row * HDIM + (kp - FDIM));
        uint32_t addr = (uint32_t)(((wo * 4 + q) * 12 + kt) * 512
                        + j * 32 + (((kl >> 3) ^ ((j >> 2) & 1)) << 4) + (kl & 7) * 2);
        *(__half2*)(smem + AW_OFF + addr) = __floats2half2_rn(v.x, v.y);
    }
    // zero h buffer (h0 = 0)
    for (int i = tid; i < 1024; i += NTHREADS)
        ((uint32_t*)(smem + HB_OFF))[i] = 0;

    // ---- per-thread frag addressing ----
    const int s = lane >> 3, jj = lane & 7;
    const int Ja = ((s & 1) << 3) + jj;
    const uint32_t a_lane = (uint32_t)(Ja * 32 + ((((s >> 1)) ^ ((Ja >> 2) & 1)) << 4));
    const int kb = ((s & 1) << 3) + jj;
    const uint32_t b_lane = (uint32_t)(kb * 32 + ((((s >> 1)) ^ ((kb >> 2) & 1)) << 4));
    const uint32_t hb_base = sb + HB_OFF + b_lane;
    const uint32_t xb_base = sb + XB_OFF + b_lane;

    const int g  = lane >> 2;             // d-frag row (0..7)
    const int cq = lane & 3;              // d-frag col pair
    const int u0 = ug * 16 + g;           // unit for jh=0 (+8 for jh=1)

    const float b0L = bih[q0 * HDIM + u0]     + bhh[q0 * HDIM + u0];
    const float b0H = bih[q0 * HDIM + u0 + 8] + bhh[q0 * HDIM + u0 + 8];
    const float b1L = bih[q1 * HDIM + u0]     + bhh[q1 * HDIM + u0];
    const float b1H = bih[q1 * HDIM + u0 + 8] + bhh[q1 * HDIM + u0 + 8];

    // h write-back addresses (gp1): k-row u, fp16 half2
    uint32_t h_addr[2][2];
#pragma unroll
    for (int nt = 0; nt < 2; nt++)
#pragma unroll
        for (int jh = 0; jh < 2; jh++)
            h_addr[nt][jh] = sb + HB_OFF
                + (uint32_t)((u0 + jh * 8) * 32
                + ((nt ^ ((g >> 2) & 1)) << 4) + cq * 4);

    // exchange addresses: float2 at ((ug*16 + j)*17 + r)*8
    uint32_t xg_addr[2][2][2];
#pragma unroll
    for (int nt = 0; nt < 2; nt++)
#pragma unroll
        for (int jh = 0; jh < 2; jh++)
#pragma unroll
            for (int ci = 0; ci < 2; ci++) {
                int j = g + jh * 8;
                int r = nt * 8 + cq * 2 + ci;
                xg_addr[nt][jh][ci] = sb + XCHG_OFF
                    + (uint32_t)(((ug * 16 + j) * 17 + r) * 8);
            }

    __syncthreads();

    // ---- preload W_hh A-fragments into registers (kt 4..11) ----
    uint32_t ah0[8][4], ah1[8][4];
#pragma unroll
    for (int kt = 0; kt < 8; kt++) {
        LDSM_X4(ah0[kt][0], ah0[kt][1], ah0[kt][2], ah0[kt][3],
                sb + AW_OFF + (uint32_t)(((ug * 4 + q0) * 12 + 4 + kt) * 512) + a_lane);
        LDSM_X4(ah1[kt][0], ah1[kt][1], ah1[kt][2], ah1[kt][3],
                sb + AW_OFF + (uint32_t)(((ug * 4 + q1) * 12 + 4 + kt) * 512) + a_lane);
    }

    // ---- x publish setup (gp0 threads: tid 0..255) ----
    const int xrow = tid & 15, kq = (tid >> 4) & 15;
    const float* xptr = x + ((size_t)(b0 + xrow) * T_STEPS) * FDIM + kq * 4;
    uint32_t xs_addr[4];
#pragma unroll
    for (int i = 0; i < 4; i++) {
        int k = kq * 4 + i;
        xs_addr[i] = sb + XB_OFF
            + (uint32_t)(k * 32 + (((xrow >> 3) ^ ((k >> 2) & 1)) << 4) + (xrow & 7) * 2);
    }

    float cs[8];
#pragma unroll
    for (int i = 0; i < 8; i++) cs[i] = 0.0f;

    float4 xr;
    if (gp == 0) {
        // publish x_0 into buffer 0
        xr = *(const float4*)xptr;
        *(__half*)(smem + (xs_addr[0] - sb)) = __float2half_rn(xr.x);
        *(__half*)(smem + (xs_addr[1] - sb)) = __float2half_rn(xr.y);
        *(__half*)(smem + (xs_addr[2] - sb)) = __float2half_rn(xr.z);
        *(__half*)(smem + (xs_addr[3] - sb)) = __float2half_rn(xr.w);
        xr = *(const float4*)(xptr + FDIM);       // x_1 for next publish
    }
    __syncthreads();                      // x_0 visible

    // ---- initial D = bias + W_ih * x_0 ----
    float D0[8], D1[8];
#pragma unroll
    for (int nt = 0; nt < 2; nt++) {
        D0[nt * 4 + 0] = b0L; D0[nt * 4 + 1] = b0L;
        D0[nt * 4 + 2] = b0H; D0[nt * 4 + 3] = b0H;
        D1[nt * 4 + 0] = b1L; D1[nt * 4 + 1] = b1L;
        D1[nt * 4 + 2] = b1H; D1[nt * 4 + 3] = b1H;
    }
#pragma unroll
    for (int kt = 0; kt < 4; kt++) {
        uint32_t v0, v1, v2, v3, a0, a1, a2, a3;
        LDSM_X4_T(v0, v1, v2, v3, xb_base + kt * 512);
        LDSM_X4(a0, a1, a2, a3,
            sb + AW_OFF + (uint32_t)(((ug * 4 + q0) * 12 + kt) * 512) + a_lane);
        MMA16816(&D0[0], a0, a1, a2, a3, v0, v1);
        MMA16816(&D0[4], a0, a1, a2, a3, v2, v3);
        LDSM_X4(a0, a1, a2, a3,
            sb + AW_OFF + (uint32_t)(((ug * 4 + q1) * 12 + kt) * 512) + a_lane);
        MMA16816(&D1[0], a0, a1, a2, a3, v0, v1);
        MMA16816(&D1[4], a0, a1, a2, a3, v2, v3);
    }

    for (int t = 0; t < T_STEPS; t++) {
        const uint32_t nb = (uint32_t)((t + 1) & 1) * 2048u;
        __syncthreads();                  // h_{t-1} visible

        // ---- h part: kt 4..11, A from registers; D += W_hh * h_{t-1} ----
#pragma unroll
        for (int kt = 0; kt < 8; kt++) {
            uint32_t v0, v1, v2, v3;
            LDSM_X4_T(v0, v1, v2, v3, hb_base + kt * 512);
            MMA16816(&D0[0], ah0[kt][0], ah0[kt][1], ah0[kt][2], ah0[kt][3], v0, v1);
            MMA16816(&D0[4], ah0[kt][0], ah0[kt][1], ah0[kt][2], ah0[kt][3], v2, v3);
            MMA16816(&D1[0], ah1[kt][0], ah1[kt][1], ah1[kt][2], ah1[kt][3], v0, v1);
            MMA16816(&D1[4], ah1[kt][0], ah1[kt][1], ah1[kt][2], ah1[kt][3], v2, v3);
        }

        float tg[8], so[8];
        if (gp == 0) {
            // sigmoid(i), sigmoid(f) -> exchange
#pragma unroll
            for (int nt = 0; nt < 2; nt++)
#pragma unroll
                for (int jh = 0; jh < 2; jh++)
#pragma unroll
                    for (int ci = 0; ci < 2; ci++) {
                        int idx = nt * 4 + jh * 2 + ci;
                        float2 v;
                        v.x = sigm_a(D0[idx]);
                        v.y = sigm_a(D1[idx]);
                        *(float2*)(smem + (xg_addr[nt][jh][ci] - sb)) = v;
                    }
            // publish x_{t+1} into buffer nb
            *(__half*)(smem + (xs_addr[0] + nb - sb)) = __float2half_rn(xr.x);
            *(__half*)(smem + (xs_addr[1] + nb - sb)) = __float2half_rn(xr.y);
            *(__half*)(smem + (xs_addr[2] + nb - sb)) = __float2half_rn(xr.z);
            *(__half*)(smem + (xs_addr[3] + nb - sb)) = __float2half_rn(xr.w);
            // prefetch x_{t+2}
            if (t + 2 < T_STEPS) xr = *(const float4*)(xptr + (size_t)(t + 2) * FDIM);
        } else {
            // tanh(g), sigmoid(o)
#pragma unroll
            for (int i = 0; i < 8; i++) {
                tg[i] = tanh_a(D0[i]);
                so[i] = sigm_a(D1[i]);
            }
        }
        __syncthreads();                  // exchange + x_{t+1} visible; h reads done

        if (gp == 1) {
#pragma unroll
            for (int nt = 0; nt < 2; nt++)
#pragma unroll
                for (int jh = 0; jh < 2; jh++) {
                    float h2[2];
#pragma unroll
                    for (int ci = 0; ci < 2; ci++) {
                        int idx = nt * 4 + jh * 2 + ci;
                        float2 sif = *(const float2*)(smem + (xg_addr[nt][jh][ci] - sb));
                        cs[idx] = sif.y * cs[idx] + sif.x * tg[idx];
                        float h = so[idx] * tanh_a(cs[idx]);
                        h2[ci] = h;
                        if (t == T_STEPS - 1) {
                            int u = u0 + jh * 8;
                            int r = nt * 8 + cq * 2 + ci;
                            *(float*)(smem + HS_OFF + (u * 16 + r) * 4) = h;
                        }
                    }
                    *(__half2*)(smem + (h_addr[nt][jh] - sb)) =
                        __floats2half2_rn(h2[0], h2[1]);
                }
        }

        // ---- tail: D = bias + W_ih * x_{t+1} (overlaps gp1 epilogue) ----
#pragma unroll
        for (int nt = 0; nt < 2; nt++) {
            D0[nt * 4 + 0] = b0L; D0[nt * 4 + 1] = b0L;
            D0[nt * 4 + 2] = b0H; D0[nt * 4 + 3] = b0H;
            D1[nt * 4 + 0] = b1L; D1[nt * 4 + 1] = b1L;
            D1[nt * 4 + 2] = b1H; D1[nt * 4 + 3] = b1H;
        }
#pragma unroll
        for (int kt = 0; kt < 4; kt++) {
            uint32_t v0, v1, v2, v3, a0, a1, a2, a3;
            LDSM_X4_T(v0, v1, v2, v3, xb_base + nb + kt * 512);
            LDSM_X4(a0, a1, a2, a3,
                sb + AW_OFF + (uint32_t)(((ug * 4 + q0) * 12 + kt) * 512) + a_lane);
            MMA16816(&D0[0], a0, a1, a2, a3, v0, v1);
            MMA16816(&D0[4], a0, a1, a2, a3, v2, v3);
            LDSM_X4(a0, a1, a2, a3,
                sb + AW_OFF + (uint32_t)(((ug * 4 + q1) * 12 + kt) * 512) + a_lane);
            MMA16816(&D1[0], a0, a1, a2, a3, v0, v1);
            MMA16816(&D1[4], a0, a1, a2, a3, v2, v3);
        }
    }
    __syncthreads();

    // ---- head: Linear(128,32) -> ReLU -> Linear(32,1) -> Sigmoid ----
    float* W1t = (float*)(smem + AW_OFF);
    float* zS  = (float*)(smem + XCHG_OFF);
    const float* hs = (const float*)(smem + HS_OFF);
    for (int i = tid; i < 32 * HDIM; i += NTHREADS) {
        int m = i >> 7, k = i & 127;
        W1t[k * 32 + m] = W1[i];
    }
    __syncthreads();
    {
        int m = tid & 31, r = (tid >> 5) & 15;
        float z = b1[m];
        for (int k = 0; k < HDIM; k++)
            z += hs[k * 16 + r] * W1t[k * 32 + m];
        zS[r * 32 + m] = fmaxf(z, 0.0f);
    }
    __syncthreads();
    if (tid < ROWS) {
        float ssum = b2[0];
#pragma unroll
        for (int mm = 0; mm < 32; mm++) ssum += zS[tid * 32 + mm] * W2[mm];
        out[b0 + tid] = sigm_exact(ssum);
    }
}

extern "C" void kernel_launch(void* const* d_in, const int* in_sizes, int n_in,
                              void* d_out, int out_size) {
    (void)in_sizes; (void)n_in; (void)out_size;
    const float* x   = (const float*)d_in[0];
    const float* Wih = (const float*)d_in[1];
    const float* Whh = (const float*)d_in[2];
    const float* bih = (const float*)d_in[3];
    const float* bhh = (const float*)d_in[4];
    const float* W1  = (const float*)d_in[5];
    const float* b1  = (const float*)d_in[6];
    const float* W2  = (const float*)d_in[7];
    const float* b2  = (const float*)d_in[8];
    float* out = (float*)d_out;

    cudaFuncSetAttribute(lstm_mma_kernel,
                         cudaFuncAttributeMaxDynamicSharedMemorySize, SMEM_TOTAL);
    lstm_mma_kernel<<<NBLOCKS, NTHREADS, SMEM_TOTAL>>>(
        x, Wih, Whh, bih, bhh, W1, b1, W2, b2, out);
}

// round 7
// speedup vs baseline: 1.3590x; 1.1522x over previous
#include <cuda_runtime.h>
#include <cuda_fp16.h>
#include <cstdint>

// LSTMClassifier B=2048,T=256,F=64,H=128 via mma.sync (HMMA) on sm_103.
// 512 threads / 16 warps per block, 16 batch rows per block.
// Gate-interleaved M packing: packed row pr = unit*4 + gate, so each m16 tile
// holds 4 units x 4 gates. Warp w owns m-tiles {2w, 2w+1} = units 8w..8w+7,
// all gates -> warp-local epilogue via a 4x4 lane butterfly transpose.
// One __syncthreads per step; h and x double-buffered.

#define T_STEPS 256
#define FDIM 64
#define HDIM 128
#define ROWS 16
#define NBLOCKS 128
#define NTHREADS 512

// smem byte offsets
#define AW_OFF   0                        // 32 mtiles x 12 kt x 512B = 196608
#define HB_OFF   196608                   // h^T double buffer: 2 x 4096
#define XB_OFF   (HB_OFF + 8192)          // x^T double buffer: 2 x 2048
#define HS_OFF   (XB_OFF + 4096)          // final h fp32 [128 u][16 r] = 8192
#define SMEM_TOTAL (HS_OFF + 8192)        // 217088

__device__ __forceinline__ uint32_t smem_u32(const void* p) {
    uint32_t a;
    asm("{ .reg .u64 t; cvta.to.shared.u64 t, %1; cvt.u32.u64 %0, t; }" : "=r"(a) : "l"(p));
    return a;
}

#define LDSM_X4(r0, r1, r2, r3, a) \
    asm volatile("ldmatrix.sync.aligned.m8n8.x4.shared.b16 {%0,%1,%2,%3}, [%4];" \
                 : "=r"(r0), "=r"(r1), "=r"(r2), "=r"(r3) : "r"(a))

#define LDSM_X4_T(r0, r1, r2, r3, a) \
    asm volatile("ldmatrix.sync.aligned.m8n8.x4.trans.shared.b16 {%0,%1,%2,%3}, [%4];" \
                 : "=r"(r0), "=r"(r1), "=r"(r2), "=r"(r3) : "r"(a))

#define MMA16816(d, a0, a1, a2, a3, b0, b1) \
    asm volatile("mma.sync.aligned.m16n8k16.row.col.f32.f16.f16.f32 " \
                 "{%0,%1,%2,%3}, {%4,%5,%6,%7}, {%8,%9}, {%0,%1,%2,%3};" \
                 : "+f"((d)[0]), "+f"((d)[1]), "+f"((d)[2]), "+f"((d)[3]) \
                 : "r"(a0), "r"(a1), "r"(a2), "r"(a3), "r"(b0), "r"(b1))

__device__ __forceinline__ float tanh_a(float x) {
    float r;
    asm("tanh.approx.f32 %0, %1;" : "=f"(r) : "f"(x));
    return r;
}
__device__ __forceinline__ float sigm_exact(float v) {
    float e = __expf(-v);
    return __fdividef(1.0f, 1.0f + e);
}

__global__ __launch_bounds__(NTHREADS, 1) void lstm_mma_kernel(
    const float* __restrict__ x,
    const float* __restrict__ Wih, const float* __restrict__ Whh,
    const float* __restrict__ bih, const float* __restrict__ bhh,
    const float* __restrict__ W1, const float* __restrict__ b1,
    const float* __restrict__ W2, const float* __restrict__ b2,
    float* __restrict__ out)
{
    extern __shared__ char smem[];
    const uint32_t sb = smem_u32(smem);
    const int tid  = threadIdx.x;
    const int wid  = tid >> 5;
    const int lane = tid & 31;
    const int b0   = blockIdx.x * ROWS;

    // ---- stage weights: packed row pr = u*4 + q  (orig row q*128+u) ----
    // Tile (mt 0..31, kt 0..11) base (mt*12+kt)*512; within tile element
    // (j = pr&15, kl): j*32 + ((kl>>3)^((j>>2)&1))*16 + (kl&7)*2.
    for (int i = tid; i < 512 * 96; i += NTHREADS) {
        int pr = i / 96;                  // packed row 0..511
        int kp = (i - pr * 96) * 2;       // 0..190 even
        int q = pr & 3, u = pr >> 2;
        int row = q * HDIM + u;           // original row
        int mt = pr >> 4, j = pr & 15;
        int kt = kp >> 4, kl = kp & 15;
        float2 v;
        if (kp < FDIM) v = *(const float2*)(Wih + row * FDIM + kp);
        else           v = *(const float2*)(Whh + row * HDIM + (kp - FDIM));
        uint32_t addr = (uint32_t)((mt * 12 + kt) * 512
                        + j * 32 + (((kl >> 3) ^ ((j >> 2) & 1)) << 4) + (kl & 7) * 2);
        *(__half2*)(smem + AW_OFF + addr) = __floats2half2_rn(v.x, v.y);
    }
    // zero h buffer 0 (h0 = 0)
    for (int i = tid; i < 1024; i += NTHREADS)
        ((uint32_t*)(smem + HB_OFF))[i] = 0;

    // ---- per-thread frag addressing ----
    const int s8 = lane >> 3, jj = lane & 7;
    const int Ja = ((s8 & 1) << 3) + jj;
    const uint32_t a_lane = (uint32_t)(Ja * 32 + ((((s8 >> 1)) ^ ((Ja >> 2) & 1)) << 4));
    const int kb = ((s8 & 1) << 3) + jj;
    const uint32_t b_lane = (uint32_t)(kb * 32 + ((((s8 >> 1)) ^ ((kb >> 2) & 1)) << 4));

    const int g  = lane >> 2;             // d-frag row 0..7
    const int cq = lane & 3;              // d-frag col pair
    const int q  = g & 3;                 // this lane's gate (pre-transpose)
    const int gh = lane >> 4;             // 0..1

    // bias per slot s = mt*2 + rh: unit u_s = wid*8 + mt*4 + rh*2 + gh
    float bias[4];
#pragma unroll
    for (int s = 0; s < 4; s++) {
        int u_s = wid * 8 + (s >> 1) * 4 + (s & 1) * 2 + gh;
        bias[s] = bih[q * HDIM + u_s] + bhh[q * HDIM + u_s];
    }

    // post-transpose: this lane owns coordinate p = q -> (mt_c, rh_c)
    const int mt_c = q >> 1, rh_c = q & 1;
    const int u_c  = wid * 8 + mt_c * 4 + rh_c * 2 + gh;
    // h writeback (half2) per nt; chunk = nt ^ mt_c
    uint32_t h_wr[2];
#pragma unroll
    for (int nt = 0; nt < 2; nt++)
        h_wr[nt] = (uint32_t)(HB_OFF + u_c * 32 + ((nt ^ mt_c) << 4) + cq * 4);

    // x publish setup (threads 0..255)
    const int xrow = tid & 15, kq = (tid >> 4) & 15;
    const float* xptr = x + ((size_t)(b0 + xrow) * T_STEPS) * FDIM + kq * 4;
    uint32_t xs_addr[4];
#pragma unroll
    for (int i = 0; i < 4; i++) {
        int k = kq * 4 + i;
        xs_addr[i] = (uint32_t)(XB_OFF
            + k * 32 + (((xrow >> 3) ^ ((k >> 2) & 1)) << 4) + (xrow & 7) * 2);
    }

    __syncthreads();                      // weights staged

    // ---- preload W_hh A-frags (kt 4..11) for this warp's 2 m-tiles ----
    uint32_t ah[2][8][4];
#pragma unroll
    for (int mt = 0; mt < 2; mt++)
#pragma unroll
        for (int kt = 0; kt < 8; kt++)
            LDSM_X4(ah[mt][kt][0], ah[mt][kt][1], ah[mt][kt][2], ah[mt][kt][3],
                sb + AW_OFF + (uint32_t)(((wid * 2 + mt) * 12 + 4 + kt) * 512) + a_lane);

    float cs[4];
#pragma unroll
    for (int i = 0; i < 4; i++) cs[i] = 0.0f;

    float4 xr;
    if (tid < 256) {
        // publish x_0 into x buffer 0
        xr = *(const float4*)xptr;
        *(__half*)(smem + xs_addr[0]) = __float2half_rn(xr.x);
        *(__half*)(smem + xs_addr[1]) = __float2half_rn(xr.y);
        *(__half*)(smem + xs_addr[2]) = __float2half_rn(xr.z);
        *(__half*)(smem + xs_addr[3]) = __float2half_rn(xr.w);
        xr = *(const float4*)(xptr + FDIM);   // x_1
    }
    __syncthreads();                      // x_0 + h_0 visible

    const int p0 = q & 1, p1 = q >> 1;    // lane position bits in 4-lane group

    for (int t = 0; t < T_STEPS; t++) {
        const uint32_t cur = (uint32_t)(t & 1);
        const uint32_t hb_cur = sb + HB_OFF + cur * 4096 + b_lane;
        const uint32_t xb_cur = sb + XB_OFF + cur * 2048 + b_lane;

        // ---- D init with bias: D[mt][nt*4 + rh*2 + ci] ----
        float D[2][8];
#pragma unroll
        for (int mt = 0; mt < 2; mt++)
#pragma unroll
            for (int nt = 0; nt < 2; nt++) {
                D[mt][nt * 4 + 0] = bias[mt * 2];     D[mt][nt * 4 + 1] = bias[mt * 2];
                D[mt][nt * 4 + 2] = bias[mt * 2 + 1]; D[mt][nt * 4 + 3] = bias[mt * 2 + 1];
            }

        // ---- x part: kt 0..3, A from smem ----
#pragma unroll
        for (int kt = 0; kt < 4; kt++) {
            uint32_t v0, v1, v2, v3;
            LDSM_X4_T(v0, v1, v2, v3, xb_cur + kt * 512);
#pragma unroll
            for (int mt = 0; mt < 2; mt++) {
                uint32_t a0, a1, a2, a3;
                LDSM_X4(a0, a1, a2, a3,
                    sb + AW_OFF + (uint32_t)(((wid * 2 + mt) * 12 + kt) * 512) + a_lane);
                MMA16816(&D[mt][0], a0, a1, a2, a3, v0, v1);
                MMA16816(&D[mt][4], a0, a1, a2, a3, v2, v3);
            }
        }
        // ---- h part: kt 4..11, A from registers ----
#pragma unroll
        for (int kt = 0; kt < 8; kt++) {
            uint32_t v0, v1, v2, v3;
            LDSM_X4_T(v0, v1, v2, v3, hb_cur + kt * 512);
#pragma unroll
            for (int mt = 0; mt < 2; mt++) {
                MMA16816(&D[mt][0], ah[mt][kt][0], ah[mt][kt][1],
                         ah[mt][kt][2], ah[mt][kt][3], v0, v1);
                MMA16816(&D[mt][4], ah[mt][kt][0], ah[mt][kt][1],
                         ah[mt][kt][2], ah[mt][kt][3], v2, v3);
            }
        }

        // ---- activation (this lane's gate q) on all 16 values ----
        // v[s][j]: s = mt*2+rh, j = nt*2+ci
        float v[4][4];
#pragma unroll
        for (int mt = 0; mt < 2; mt++)
#pragma unroll
            for (int nt = 0; nt < 2; nt++)
#pragma unroll
                for (int rh = 0; rh < 2; rh++)
#pragma unroll
                    for (int ci = 0; ci < 2; ci++) {
                        float d = D[mt][nt * 4 + rh * 2 + ci];
                        float a = (q == 2) ? d : 0.5f * d;
                        float th = tanh_a(a);
                        v[mt * 2 + rh][nt * 2 + ci] =
                            (q == 2) ? th : fmaf(th, 0.5f, 0.5f);
                    }

        // ---- 4x4 lane-group transpose: gates gather to cell owner ----
        // Step A: p0 <-> s0 (xor 4)
#pragma unroll
        for (int s1 = 0; s1 < 2; s1++)
#pragma unroll
            for (int j = 0; j < 4; j++) {
                float a0 = v[s1 * 2][j], a1 = v[s1 * 2 + 1][j];
                float send = p0 ? a0 : a1;
                float got = __shfl_xor_sync(0xFFFFFFFFu, send, 4);
                v[s1 * 2][j]     = p0 ? got : a0;
                v[s1 * 2 + 1][j] = p0 ? a1 : got;
            }
        // Step B: p1 <-> s1 (xor 8)
#pragma unroll
        for (int s0 = 0; s0 < 2; s0++)
#pragma unroll
            for (int j = 0; j < 4; j++) {
                float a0 = v[s0][j], a1 = v[2 + s0][j];
                float send = p1 ? a0 : a1;
                float got = __shfl_xor_sync(0xFFFFFFFFu, send, 8);
                v[s0][j]     = p1 ? got : a0;
                v[2 + s0][j] = p1 ? a1 : got;
            }
        // now v[gate][j] for this lane's 4 cells (coordinate p=q), j=(nt,ci)

        // ---- cell update + h writeback (buffer cur^1) ----
        float hv[4];
#pragma unroll
        for (int j = 0; j < 4; j++) {
            cs[j] = v[1][j] * cs[j] + v[0][j] * v[2][j];
            hv[j] = v[3][j] * tanh_a(cs[j]);
        }
        const uint32_t nxt = (cur ^ 1u) * 4096u;
        *(__half2*)(smem + h_wr[0] + nxt) = __floats2half2_rn(hv[0], hv[1]);
        *(__half2*)(smem + h_wr[1] + nxt) = __floats2half2_rn(hv[2], hv[3]);
        if (t == T_STEPS - 1) {
#pragma unroll
            for (int j = 0; j < 4; j++) {
                int r = (j >> 1) * 8 + cq * 2 + (j & 1);
                *(float*)(smem + HS_OFF + (u_c * 16 + r) * 4) = hv[j];
            }
        }

        // ---- publish x_{t+1} into buffer cur^1 ----
        if (tid < 256) {
            const uint32_t nb = (cur ^ 1u) * 2048u;
            *(__half*)(smem + xs_addr[0] + nb) = __float2half_rn(xr.x);
            *(__half*)(smem + xs_addr[1] + nb) = __float2half_rn(xr.y);
            *(__half*)(smem + xs_addr[2] + nb) = __float2half_rn(xr.z);
            *(__half*)(smem + xs_addr[3] + nb) = __float2half_rn(xr.w);
            if (t + 2 < T_STEPS) xr = *(const float4*)(xptr + (size_t)(t + 2) * FDIM);
        }
        __syncthreads();                  // h_{t}, x_{t+1} visible; reads done
    }

    // ---- head: Linear(128,32) -> ReLU -> Linear(32,1) -> Sigmoid ----
    float* W1t = (float*)(smem + AW_OFF);
    float* zS  = (float*)(smem + HB_OFF);
    const float* hs = (const float*)(smem + HS_OFF);
    for (int i = tid; i < 32 * HDIM; i += NTHREADS) {
        int m = i >> 7, k = i & 127;
        W1t[k * 32 + m] = W1[i];
    }
    __syncthreads();
    {
        int m = tid & 31, r = (tid >> 5) & 15;
        float z = b1[m];
        for (int k = 0; k < HDIM; k++)
            z += hs[k * 16 + r] * W1t[k * 32 + m];
        zS[r * 32 + m] = fmaxf(z, 0.0f);
    }
    __syncthreads();
    if (tid < ROWS) {
        float ssum = b2[0];
#pragma unroll
        for (int mm = 0; mm < 32; mm++) ssum += zS[tid * 32 + mm] * W2[mm];
        out[b0 + tid] = sigm_exact(ssum);
    }
}

extern "C" void kernel_launch(void* const* d_in, const int* in_sizes, int n_in,
                              void* d_out, int out_size) {
    (void)in_sizes; (void)n_in; (void)out_size;
    const float* x   = (const float*)d_in[0];
    const float* Wih = (const float*)d_in[1];
    const float* Whh = (const float*)d_in[2];
    const float* bih = (const float*)d_in[3];
    const float* bhh = (const float*)d_in[4];
    const float* W1  = (const float*)d_in[5];
    const float* b1  = (const float*)d_in[6];
    const float* W2  = (const float*)d_in[7];
    const float* b2  = (const float*)d_in[8];
    float* out = (float*)d_out;

    cudaFuncSetAttribute(lstm_mma_kernel,
                         cudaFuncAttributeMaxDynamicSharedMemorySize, SMEM_TOTAL);
    lstm_mma_kernel<<<NBLOCKS, NTHREADS, SMEM_TOTAL>>>(
        x, Wih, Whh, bih, bhh, W1, b1, W2, b2, out);
}